// round 5
// baseline (speedup 1.0000x reference)
#include <cuda_runtime.h>
#include <cuda_bf16.h>
#include <math.h>

// Shapes (fixed per reference): B=512, T=256, F=D=1024
#define BB 512
#define TT 256
#define FF 1024

typedef unsigned long long ull;

// Scratch (allocation-free rule: __device__ globals)
__device__ float g_q[BB * FF];
__device__ float g_u[BB * FF];
__device__ float g_c[BB * FF];
__device__ float g_part[2][BB * FF];   // split-K partials

// ---------------- packed f32x2 helpers (SASS FFMA2) --------------------------
__device__ __forceinline__ void ffma2(ull& d, ull a, ull b) {
    asm("fma.rn.f32x2 %0, %1, %2, %0;" : "+l"(d) : "l"(a), "l"(b));
}
__device__ __forceinline__ float2 unpack2(ull v) {
    float2 f;
    asm("mov.b64 {%0, %1}, %2;" : "=f"(f.x), "=f"(f.y) : "l"(v));
    return f;
}

// ---------------------------------------------------------------------------
// Split-K fp32 GEMM, FFMA2 inner loop with ZERO packing movs:
//   - As[k][m] k-major: a m-pair read as one ld.shared.b64
//   - Bs holds pre-DUPLICATED (b,b) pairs, tx-swizzled so the 8-float-stride
//     LDS.128 reads are bank-conflict-free. Column n lives at float offset
//     g(n) = 2n + 4*(n>>4); thread tx reads 8 floats at 8*tx + 4*(tx>>2).
// Y_part[z] = X[:, z*K/2:(z+1)*K/2] * op(W)  (blockIdx.z = z)
//   TRANSB=true : op(W) = W^T (W is [N,K]);  false: op(W) = W (W is [K,N])
// 64x64 tile, BK=16, 256 threads, 4x4 per thread (2 m-pairs x 4 n).
// ---------------------------------------------------------------------------
template <bool TRANSB>
__global__ __launch_bounds__(256)
void gemm_splitk(const float* __restrict__ X, const float* __restrict__ W,
                 float* __restrict__ Ypart, int M, int N, int K)
{
    __shared__ float As[2][16][68];
    __shared__ float Bs[2][16][144];

    const int tid = threadIdx.x;
    const int tx = tid & 15;       // n sub-tile
    const int ty = tid >> 4;       // m sub-tile
    const int m0 = blockIdx.y * 64;
    const int n0 = blockIdx.x * 64;
    const int KH = K >> 1;
    const int kz0 = blockIdx.z * KH;

    // global load coordinates
    const int ar  = tid >> 2;          // row within 64 (A and NT-B)
    const int ac4 = (tid & 3) * 4;     // k offset within 16
    const int bk  = tid >> 4;          // k row (NN-B)
    const int bn4 = (tid & 15) * 4;    // n offset (NN-B)

    const float* Aptr = X + (size_t)(m0 + ar) * K + kz0 + ac4;
    const float* Bptr = TRANSB ? (W + (size_t)(n0 + ar) * K + kz0 + ac4)
                               : (W + (size_t)(kz0 + bk) * N + n0 + bn4);

    // dup-store offsets
    const int nt_g = 2 * ar + 4 * (ar >> 4);           // TRANSB: n = ar
    const int nn_g = 2 * bn4 + 4 * (bn4 >> 4);         // NN: base of 4 cols (contiguous)

    ull acc[2][4];
#pragma unroll
    for (int i = 0; i < 2; i++)
#pragma unroll
        for (int j = 0; j < 4; j++) acc[i][j] = 0ull;

    // ---- prologue: stage 0
    {
        float4 va = *reinterpret_cast<const float4*>(Aptr);
        As[0][ac4 + 0][ar] = va.x;
        As[0][ac4 + 1][ar] = va.y;
        As[0][ac4 + 2][ar] = va.z;
        As[0][ac4 + 3][ar] = va.w;
        float4 vb = *reinterpret_cast<const float4*>(Bptr);
        if (TRANSB) {
            *reinterpret_cast<float2*>(&Bs[0][ac4 + 0][nt_g]) = make_float2(vb.x, vb.x);
            *reinterpret_cast<float2*>(&Bs[0][ac4 + 1][nt_g]) = make_float2(vb.y, vb.y);
            *reinterpret_cast<float2*>(&Bs[0][ac4 + 2][nt_g]) = make_float2(vb.z, vb.z);
            *reinterpret_cast<float2*>(&Bs[0][ac4 + 3][nt_g]) = make_float2(vb.w, vb.w);
        } else {
            *reinterpret_cast<float4*>(&Bs[0][bk][nn_g])     = make_float4(vb.x, vb.x, vb.y, vb.y);
            *reinterpret_cast<float4*>(&Bs[0][bk][nn_g + 4]) = make_float4(vb.z, vb.z, vb.w, vb.w);
        }
    }
    __syncthreads();

    int s = 0;
    for (int kt = 16;; kt += 16) {
        float4 va, vb;
        const bool more = (kt < KH);
        if (more) {
            va = *reinterpret_cast<const float4*>(Aptr + kt);
            vb = *reinterpret_cast<const float4*>(Bptr + (TRANSB ? kt : (size_t)kt * N));
        }

        // ---- compute current stage: 12 instr / 32 MACs per k-step
#pragma unroll
        for (int k = 0; k < 16; k++) {
            ull a01 = *reinterpret_cast<const ull*>(&As[s][k][ty * 4]);
            ull a23 = *reinterpret_cast<const ull*>(&As[s][k][ty * 4 + 2]);
            const ulonglong2* bp =
                reinterpret_cast<const ulonglong2*>(&Bs[s][k][8 * tx + 4 * (tx >> 2)]);
            ulonglong2 b01 = bp[0];   // {b0,b0},{b1,b1}
            ulonglong2 b23 = bp[1];   // {b2,b2},{b3,b3}
            ffma2(acc[0][0], a01, b01.x); ffma2(acc[0][1], a01, b01.y);
            ffma2(acc[0][2], a01, b23.x); ffma2(acc[0][3], a01, b23.y);
            ffma2(acc[1][0], a23, b01.x); ffma2(acc[1][1], a23, b01.y);
            ffma2(acc[1][2], a23, b23.x); ffma2(acc[1][3], a23, b23.y);
        }
        if (!more) break;

        // ---- store next stage
        const int ns = s ^ 1;
        As[ns][ac4 + 0][ar] = va.x;
        As[ns][ac4 + 1][ar] = va.y;
        As[ns][ac4 + 2][ar] = va.z;
        As[ns][ac4 + 3][ar] = va.w;
        if (TRANSB) {
            *reinterpret_cast<float2*>(&Bs[ns][ac4 + 0][nt_g]) = make_float2(vb.x, vb.x);
            *reinterpret_cast<float2*>(&Bs[ns][ac4 + 1][nt_g]) = make_float2(vb.y, vb.y);
            *reinterpret_cast<float2*>(&Bs[ns][ac4 + 2][nt_g]) = make_float2(vb.z, vb.z);
            *reinterpret_cast<float2*>(&Bs[ns][ac4 + 3][nt_g]) = make_float2(vb.w, vb.w);
        } else {
            *reinterpret_cast<float4*>(&Bs[ns][bk][nn_g])     = make_float4(vb.x, vb.x, vb.y, vb.y);
            *reinterpret_cast<float4*>(&Bs[ns][bk][nn_g + 4]) = make_float4(vb.z, vb.z, vb.w, vb.w);
        }
        __syncthreads();
        s = ns;
    }

    // epilogue: acc[mp][n] packs rows (ty*4+2mp, ty*4+2mp+1) for col n
    float* out = Ypart + (size_t)blockIdx.z * ((size_t)M * N);
#pragma unroll
    for (int mp = 0; mp < 2; mp++) {
        float2 c0 = unpack2(acc[mp][0]);
        float2 c1 = unpack2(acc[mp][1]);
        float2 c2 = unpack2(acc[mp][2]);
        float2 c3 = unpack2(acc[mp][3]);
        float4 lo = make_float4(c0.x, c1.x, c2.x, c3.x);
        float4 hi = make_float4(c0.y, c1.y, c2.y, c3.y);
        *reinterpret_cast<float4*>(out + (size_t)(m0 + ty * 4 + 2 * mp)     * N + n0 + tx * 4) = lo;
        *reinterpret_cast<float4*>(out + (size_t)(m0 + ty * 4 + 2 * mp + 1) * N + n0 + tx * 4) = hi;
    }
}

// ---------------------------------------------------------------------------
// reduce: out = part0 + part1 (+ bias), vectorized. BB*FF/4 float4 elements.
// ---------------------------------------------------------------------------
__global__ __launch_bounds__(256)
void reduce2(const float4* __restrict__ p0, const float4* __restrict__ p1,
             const float4* __restrict__ bias, float4* __restrict__ out)
{
    const int i = blockIdx.x * 256 + threadIdx.x;
    float4 a = p0[i];
    float4 b = p1[i];
    float4 r = make_float4(a.x + b.x, a.y + b.y, a.z + b.z, a.w + b.w);
    if (bias) {
        float4 bv = bias[i & (FF / 4 - 1)];
        r.x += bv.x; r.y += bv.y; r.z += bv.z; r.w += bv.w;
    }
    out[i] = r;
}

// ---------------------------------------------------------------------------
// Fused single-query attention, online softmax, single HBM pass over p,
// 2-stage cp.async pipeline (8 t-rows = 32KB per stage). (unchanged from R2)
// ---------------------------------------------------------------------------
#define TILE_F4 (8 * (FF / 4))   // 2048 float4 per stage

__device__ __forceinline__ void cp_async16(void* smem_dst, const void* gsrc) {
    unsigned saddr = (unsigned)__cvta_generic_to_shared(smem_dst);
    asm volatile("cp.async.cg.shared.global [%0], [%1], 16;"
                 :: "r"(saddr), "l"(gsrc));
}
__device__ __forceinline__ void cp_commit() {
    asm volatile("cp.async.commit_group;");
}
template <int N>
__device__ __forceinline__ void cp_wait() {
    asm volatile("cp.async.wait_group %0;" :: "n"(N));
}

__global__ __launch_bounds__(256)
void attn_kernel(const float* __restrict__ u, const float* __restrict__ p,
                 float* __restrict__ c)
{
    extern __shared__ float4 smem[];
    float4* u_s   = smem;               // 256 float4 (4KB)
    float4* tiles = smem + 256;         // 2 stages x 2048 float4 (64KB)
    float*  s_sm  = (float*)(smem + 256 + 2 * TILE_F4);  // 8 floats

    const int b    = blockIdx.x;
    const int tid  = threadIdx.x;
    const int lane = tid & 31;
    const int w    = tid >> 5;

    u_s[tid] = reinterpret_cast<const float4*>(u + (size_t)b * FF)[tid];

    const float4* pb = reinterpret_cast<const float4*>(p + (size_t)b * TT * FF);

    // prologue: tile 0 -> stage 0
#pragma unroll
    for (int j = 0; j < 8; j++)
        cp_async16(&tiles[j * 256 + tid], &pb[j * 256 + tid]);
    cp_commit();

    float4 acc = make_float4(0.f, 0.f, 0.f, 0.f);
    float m = -INFINITY;
    float l = 0.f;

    for (int it = 0; it < TT / 8; it++) {
        const int s = it & 1;
        if (it + 1 < TT / 8) {
            const float4* src = pb + (it + 1) * TILE_F4;
            float4* dst = tiles + (s ^ 1) * TILE_F4;
#pragma unroll
            for (int j = 0; j < 8; j++)
                cp_async16(&dst[j * 256 + tid], &src[j * 256 + tid]);
            cp_commit();
            cp_wait<1>();
        } else {
            cp_wait<0>();
        }
        __syncthreads();

        const float4* tile = tiles + s * TILE_F4;

        // scores: warp w computes dot(u, row w)
        float partial = 0.f;
#pragma unroll
        for (int k = 0; k < 8; k++) {
            float4 a  = tile[w * 256 + k * 32 + lane];
            float4 uu = u_s[k * 32 + lane];
            partial += a.x * uu.x + a.y * uu.y + a.z * uu.z + a.w * uu.w;
        }
#pragma unroll
        for (int off = 16; off; off >>= 1)
            partial += __shfl_xor_sync(0xffffffffu, partial, off);
        if (lane == 0) s_sm[w] = partial;
        __syncthreads();

        // online softmax update (redundant per thread, identical values)
        float s0[8], wv[8];
        float tmax = -INFINITY;
#pragma unroll
        for (int i = 0; i < 8; i++) { s0[i] = s_sm[i]; tmax = fmaxf(tmax, s0[i]); }
        float m_new = fmaxf(m, tmax);
        float cf = __expf(m - m_new);   // it=0: exp(-inf)=0, acc is 0 anyway
        float wsum = 0.f;
#pragma unroll
        for (int i = 0; i < 8; i++) { wv[i] = __expf(s0[i] - m_new); wsum += wv[i]; }
        l = l * cf + wsum;
        m = m_new;
        acc.x *= cf; acc.y *= cf; acc.z *= cf; acc.w *= cf;

        // accumulate weighted rows; thread owns features [tid*4, tid*4+4)
#pragma unroll
        for (int i = 0; i < 8; i++) {
            float4 v = tile[i * 256 + tid];
            acc.x += wv[i] * v.x;
            acc.y += wv[i] * v.y;
            acc.z += wv[i] * v.z;
            acc.w += wv[i] * v.w;
        }
        __syncthreads();   // stage s free for the cp.async issued at it+2
    }

    float inv = 1.f / l;
    reinterpret_cast<float4*>(c + (size_t)b * FF)[tid] =
        make_float4(acc.x * inv, acc.y * inv, acc.z * inv, acc.w * inv);
}

// ---------------------------------------------------------------------------
// kernel_launch
// Inputs: 0=z_state[512,1024] 1=past_predictions[512,256,1024]
//         2=Wq[1024,1024] 3=Wk[1024,1024] 4=Wv[1024,1024]
//         5=bq[1024] 6=bk[1024] 7=bv[1024]
// Output: context [512,1024] fp32
// ---------------------------------------------------------------------------
extern "C" void kernel_launch(void* const* d_in, const int* in_sizes, int n_in,
                              void* d_out, int out_size)
{
    const float* z    = (const float*)d_in[0];
    const float* past = (const float*)d_in[1];
    const float* Wq   = (const float*)d_in[2];
    const float* Wk   = (const float*)d_in[3];
    const float* Wv   = (const float*)d_in[4];
    const float* bq   = (const float*)d_in[5];
    // bk (d_in[6]) is softmax-invariant (constant per-b score shift) — unused.
    const float* bv   = (const float*)d_in[7];
    float* out = (float*)d_out;

    void *qp, *up, *cp, *pp;
    cudaGetSymbolAddress(&qp, g_q);
    cudaGetSymbolAddress(&up, g_u);
    cudaGetSymbolAddress(&cp, g_c);
    cudaGetSymbolAddress(&pp, g_part);
    float* q_buf = (float*)qp;
    float* u_buf = (float*)up;
    float* c_buf = (float*)cp;
    float4* part0 = (float4*)pp;
    float4* part1 = part0 + (BB * FF / 4);

    const int attn_smem = (256 + 2 * TILE_F4) * sizeof(float4) + 32 * sizeof(float);
    cudaFuncSetAttribute(attn_kernel,
                         cudaFuncAttributeMaxDynamicSharedMemorySize, attn_smem);

    dim3 gg(FF / 64, BB / 64, 2);      // (16, 8, 2) = 256 blocks
    const int rg = (BB * FF / 4) / 256;  // 512 blocks

    // q = z @ Wq^T + bq
    gemm_splitk<true><<<gg, 256>>>(z, Wq, (float*)part0, BB, FF, FF);
    reduce2<<<rg, 256>>>(part0, part1, (const float4*)bq, (float4*)q_buf);
    // u = q @ Wk
    gemm_splitk<false><<<gg, 256>>>(q_buf, Wk, (float*)part0, BB, FF, FF);
    reduce2<<<rg, 256>>>(part0, part1, nullptr, (float4*)u_buf);
    // c[b] = softmax_t(u[b].p[b,t]) . p[b]
    attn_kernel<<<BB, 256, attn_smem>>>(u_buf, past, c_buf);
    // out = c @ Wv^T + bv
    gemm_splitk<true><<<gg, 256>>>(c_buf, Wv, (float*)part0, BB, FF, FF);
    reduce2<<<rg, 256>>>(part0, part1, (const float4*)bv, (float4*)out);
}

// round 9
// speedup vs baseline: 1.1696x; 1.1696x over previous
#include <cuda_runtime.h>
#include <cuda_bf16.h>
#include <math.h>
#include <cstdint>

// Shapes (fixed per reference): B=512, T=256, F=D=1024
#define BB 512
#define TT 256
#define FF 1024
// 3-term bf16 split (Markidis): K = [hi|lo|hi] (A side) x [hi|hi|lo] (B side)
#define KS 3072

// ---------------- scratch (__device__ globals; no allocs allowed) -----------
__device__ __align__(16) __nv_bfloat16 g_xa[BB * KS];  // split(z) / split(c), A-side
__device__ __align__(16) __nv_bfloat16 g_xb[BB * KS];  // split(q), A-side (GEMM1 epi)
__device__ __align__(16) __nv_bfloat16 g_w2[FF * KS];  // split(W*), B-side (reused)
__device__ float g_u[BB * FF];
__device__ float g_c[BB * FF];

// ---------------- ptx helpers ----------------------------------------------
__device__ __forceinline__ uint32_t smem_u32(const void* p) {
    uint32_t a;
    asm("{ .reg .u64 t; cvta.to.shared.u64 t, %1; cvt.u32.u64 %0, t; }"
        : "=r"(a) : "l"(p));
    return a;
}
__device__ __forceinline__ void cpa16(uint32_t dst, const void* src) {
    asm volatile("cp.async.cg.shared.global [%0], [%1], 16;" :: "r"(dst), "l"(src));
}
#define CPA_COMMIT() asm volatile("cp.async.commit_group;" ::: "memory")

__device__ __forceinline__ void ldsm_x4(uint32_t (&r)[4], uint32_t addr) {
    asm volatile("ldmatrix.sync.aligned.m8n8.x4.shared.b16 {%0,%1,%2,%3}, [%4];"
                 : "=r"(r[0]), "=r"(r[1]), "=r"(r[2]), "=r"(r[3]) : "r"(addr));
}
__device__ __forceinline__ void mma_bf16(float (&d)[4], const uint32_t (&a)[4],
                                         uint32_t b0, uint32_t b1) {
    asm volatile(
        "mma.sync.aligned.m16n8k16.row.col.f32.bf16.bf16.f32 "
        "{%0,%1,%2,%3}, {%4,%5,%6,%7}, {%8,%9}, {%0,%1,%2,%3};"
        : "+f"(d[0]), "+f"(d[1]), "+f"(d[2]), "+f"(d[3])
        : "r"(a[0]), "r"(a[1]), "r"(a[2]), "r"(a[3]), "r"(b0), "r"(b1));
}

// ---------------- fp32 -> bf16 hi/lo split ----------------------------------
__device__ __forceinline__ void split1(float x, __nv_bfloat16& h, __nv_bfloat16& l) {
    h = __float2bfloat16(x);
    l = __float2bfloat16(x - __bfloat162float(h));
}
__device__ __forceinline__ uint32_t pack_bf(__nv_bfloat16 a, __nv_bfloat16 b) {
    return (uint32_t)__bfloat16_as_ushort(a) | ((uint32_t)__bfloat16_as_ushort(b) << 16);
}

// in: fp32 [R][1024] -> out bf16 [R][3072].
// BSIDE=false: [hi | lo | hi] (activations).  BSIDE=true: [hi | hi | lo] (weights).
// grid = R blocks, 256 thr (one float4 per thread).
template <bool BSIDE>
__global__ __launch_bounds__(256)
void split_mat(const float4* __restrict__ in, __nv_bfloat16* __restrict__ out)
{
    int i = blockIdx.x * 256 + threadIdx.x;
    float4 v = in[i];
    int r = i >> 8, c4 = (i & 255) * 4;
    __nv_bfloat16 h0, h1, h2, h3, l0, l1, l2, l3;
    split1(v.x, h0, l0); split1(v.y, h1, l1);
    split1(v.z, h2, l2); split1(v.w, h3, l3);
    uint2 hv, lv;
    hv.x = pack_bf(h0, h1); hv.y = pack_bf(h2, h3);
    lv.x = pack_bf(l0, l1); lv.y = pack_bf(l2, l3);
    __nv_bfloat16* base = out + (size_t)r * KS + c4;
    *reinterpret_cast<uint2*>(base)        = hv;                    // seg0: hi
    *reinterpret_cast<uint2*>(base + 1024) = BSIDE ? hv : lv;       // seg1
    *reinterpret_cast<uint2*>(base + 2048) = BSIDE ? lv : hv;       // seg2
}

// Wk is [K=1024][N=1024]; out[n] = B-side split of column n: [hi|hi|lo].
// grid (32,32), 256 thr.
__global__ __launch_bounds__(256)
void splitT_mat(const float* __restrict__ W, __nv_bfloat16* __restrict__ out)
{
    __shared__ float t[32][33];
    int tx = threadIdx.x & 31, ty = threadIdx.x >> 5;   // ty 0..7
    int k0 = blockIdx.x * 32, n0 = blockIdx.y * 32;
#pragma unroll
    for (int i = 0; i < 4; i++)
        t[ty * 4 + i][tx] = W[(size_t)(k0 + ty * 4 + i) * FF + n0 + tx];
    __syncthreads();
#pragma unroll
    for (int i = 0; i < 4; i++) {
        int nn = ty * 4 + i;
        float v = t[tx][nn];          // = W[k0+tx][n0+nn]
        __nv_bfloat16 h, l;
        split1(v, h, l);
        __nv_bfloat16* base = out + (size_t)(n0 + nn) * KS + k0 + tx;
        base[0]    = h;
        base[1024] = h;
        base[2048] = l;
    }
}

// ---------------------------------------------------------------------------
// HMMA bf16 NT GEMM:  D[512][1024] = A2[512][3072] @ B2[1024][3072]^T, fp32 acc
// CTA tile 128(M)x64(N), 8 warps (4M x 2N), warp tile 32x32.
// BK=32 bf16 per stage, 4-stage cp.async ring. smem pitch 80B (20-bank stride:
// ldmatrix row addrs and fragment loads conflict-free).
// OUTSPLIT: epilogue writes A-side bf16 split [M][3072] instead of fp32 [M][1024].
// ---------------------------------------------------------------------------
#define PITCH 80                        // bytes per 32-bf16 row (64B data + 16B pad)
#define A_BYTES (128 * PITCH)           // 10240
#define B_BYTES (64 * PITCH)            // 5120
#define STAGE_BYTES (A_BYTES + B_BYTES) // 15360
#define SMEM_GEMM (4 * STAGE_BYTES)     // 61440
#define NKT (KS / 32)                   // 96 k-tiles

__device__ __forceinline__ void load_chunk_h(
    const __nv_bfloat16* __restrict__ A2, const __nv_bfloat16* __restrict__ B2,
    uint32_t stage_smem, int m0, int n0, int kt_el, int tid)
{
    // 512 A chunks (128 rows x 4x16B) + 256 B chunks (64 rows x 4x16B), 3/thread
#pragma unroll
    for (int i = 0; i < 3; i++) {
        int ch = i * 256 + tid;
        if (ch < 512) {
            int row = ch >> 2, j = ch & 3;
            cpa16(stage_smem + row * PITCH + j * 16,
                  A2 + (size_t)(m0 + row) * KS + kt_el + j * 8);
        } else {
            int cb = ch - 512;
            int row = cb >> 2, j = cb & 3;
            cpa16(stage_smem + A_BYTES + row * PITCH + j * 16,
                  B2 + (size_t)(n0 + row) * KS + kt_el + j * 8);
        }
    }
}

template <bool HASBIAS, bool OUTSPLIT>
__global__ __launch_bounds__(256)
void mma_gemm(const __nv_bfloat16* __restrict__ A2,
              const __nv_bfloat16* __restrict__ B2,
              const float* __restrict__ bias, void* __restrict__ Out)
{
    extern __shared__ char smem[];
    const uint32_t sb = smem_u32(smem);
    const int tid  = threadIdx.x;
    const int wid  = tid >> 5;
    const int lane = tid & 31;
    const int wm = wid & 3;        // 4 M groups of 32 rows
    const int wn = wid >> 2;       // 2 N groups of 32 cols
    const int m0 = blockIdx.y * 128;
    const int n0 = blockIdx.x * 64;

    // per-thread ldmatrix byte offsets (within a stage, k16=0)
    const int q  = lane >> 3;      // quad 0..3
    const int lr = lane & 7;
    uint32_t a_off[2], b_off[2];
    // A frag mf: matrices [rows0-7 k0-7, rows8-15 k0-7, rows0-7 k8-15, rows8-15 k8-15]
#pragma unroll
    for (int mf = 0; mf < 2; mf++)
        a_off[mf] = (uint32_t)((wm * 32 + mf * 16 + (q & 1) * 8 + lr) * PITCH
                               + (q >> 1) * 16);
    // B frag-pair nf2: matrices [n0-7 k0-7, n0-7 k8-15, n8-15 k0-7, n8-15 k8-15]
#pragma unroll
    for (int nf2 = 0; nf2 < 2; nf2++)
        b_off[nf2] = (uint32_t)(A_BYTES
                               + (wn * 32 + nf2 * 16 + (q >> 1) * 8 + lr) * PITCH
                               + (q & 1) * 16);

    float acc[2][4][4];
#pragma unroll
    for (int mf = 0; mf < 2; mf++)
#pragma unroll
        for (int nf = 0; nf < 4; nf++)
#pragma unroll
            for (int e = 0; e < 4; e++) acc[mf][nf][e] = 0.f;

    // prologue: stages 0..2
#pragma unroll
    for (int c = 0; c < 3; c++) {
        load_chunk_h(A2, B2, sb + c * STAGE_BYTES, m0, n0, c * 32, tid);
        CPA_COMMIT();
    }

    for (int c = 0; c < NKT; c++) {
        const uint32_t st = sb + (c & 3) * STAGE_BYTES;
        asm volatile("cp.async.wait_group 2;" ::: "memory");
        __syncthreads();

        if (c + 3 < NKT)
            load_chunk_h(A2, B2, sb + ((c + 3) & 3) * STAGE_BYTES,
                         m0, n0, (c + 3) * 32, tid);
        CPA_COMMIT();

#pragma unroll
        for (int k16 = 0; k16 < 2; k16++) {
            const uint32_t kb = st + k16 * 32;
            uint32_t a0[4], a1[4], b0[4], b1[4];
            ldsm_x4(a0, kb + a_off[0]);
            ldsm_x4(a1, kb + a_off[1]);
            ldsm_x4(b0, kb + b_off[0]);   // n0..15: (k0-7, k8-15) x (n0-7, n8-15)
            ldsm_x4(b1, kb + b_off[1]);   // n16..31
            mma_bf16(acc[0][0], a0, b0[0], b0[1]);
            mma_bf16(acc[0][1], a0, b0[2], b0[3]);
            mma_bf16(acc[0][2], a0, b1[0], b1[1]);
            mma_bf16(acc[0][3], a0, b1[2], b1[3]);
            mma_bf16(acc[1][0], a1, b0[0], b0[1]);
            mma_bf16(acc[1][1], a1, b0[2], b0[3]);
            mma_bf16(acc[1][2], a1, b1[0], b1[1]);
            mma_bf16(acc[1][3], a1, b1[2], b1[3]);
        }
        __syncthreads();   // all reads of chunk c done before its stage is reloaded
    }

    // epilogue: thread t of warp -> rows wm*32+mf*16+{t/4, t/4+8},
    //           cols wn*32+nf*8+2*(t%4)+{0,1}
    const int r0 = wm * 32 + (lane >> 2);
    const int cbase = wn * 32 + 2 * (lane & 3);
#pragma unroll
    for (int mf = 0; mf < 2; mf++) {
#pragma unroll
        for (int nf = 0; nf < 4; nf++) {
            const int col = n0 + cbase + nf * 8;
            float bx = 0.f, by = 0.f;
            if (HASBIAS) { bx = bias[col]; by = bias[col + 1]; }
            const int rowA = m0 + r0 + mf * 16;
            const int rowB = rowA + 8;
            float d0 = acc[mf][nf][0] + bx, d1 = acc[mf][nf][1] + by;
            float d2 = acc[mf][nf][2] + bx, d3 = acc[mf][nf][3] + by;
            if (OUTSPLIT) {
                // A-side split layout: [hi | lo | hi]
                __nv_bfloat16* o2 = (__nv_bfloat16*)Out;
                __nv_bfloat16 h0, h1, h2, h3, l0, l1, l2, l3;
                split1(d0, h0, l0); split1(d1, h1, l1);
                split1(d2, h2, l2); split1(d3, h3, l3);
                uint32_t hA = pack_bf(h0, h1), lA = pack_bf(l0, l1);
                uint32_t hB = pack_bf(h2, h3), lB = pack_bf(l2, l3);
                __nv_bfloat16* pA = o2 + (size_t)rowA * KS + col;
                __nv_bfloat16* pB = o2 + (size_t)rowB * KS + col;
                *reinterpret_cast<uint32_t*>(pA)        = hA;
                *reinterpret_cast<uint32_t*>(pA + 1024) = lA;
                *reinterpret_cast<uint32_t*>(pA + 2048) = hA;
                *reinterpret_cast<uint32_t*>(pB)        = hB;
                *reinterpret_cast<uint32_t*>(pB + 1024) = lB;
                *reinterpret_cast<uint32_t*>(pB + 2048) = hB;
            } else {
                float* o = (float*)Out;
                *reinterpret_cast<float2*>(o + (size_t)rowA * FF + col) = make_float2(d0, d1);
                *reinterpret_cast<float2*>(o + (size_t)rowB * FF + col) = make_float2(d2, d3);
            }
        }
    }
}

// ---------------------------------------------------------------------------
// Fused single-query attention (unchanged: 2-stage cp.async, online softmax,
// one HBM pass over past_predictions).
// ---------------------------------------------------------------------------
#define TILE_F4 (8 * (FF / 4))

__global__ __launch_bounds__(256)
void attn_kernel(const float* __restrict__ u, const float* __restrict__ p,
                 float* __restrict__ c)
{
    extern __shared__ float4 smem4[];
    float4* u_s   = smem4;
    float4* tiles = smem4 + 256;
    float*  s_sm  = (float*)(smem4 + 256 + 2 * TILE_F4);

    const int b    = blockIdx.x;
    const int tid  = threadIdx.x;
    const int lane = tid & 31;
    const int w    = tid >> 5;

    u_s[tid] = reinterpret_cast<const float4*>(u + (size_t)b * FF)[tid];

    const float4* pb = reinterpret_cast<const float4*>(p + (size_t)b * TT * FF);

#pragma unroll
    for (int j = 0; j < 8; j++)
        cpa16(smem_u32(&tiles[j * 256 + tid]), &pb[j * 256 + tid]);
    CPA_COMMIT();

    float4 acc = make_float4(0.f, 0.f, 0.f, 0.f);
    float m = -INFINITY;
    float l = 0.f;

    for (int it = 0; it < TT / 8; it++) {
        const int s = it & 1;
        if (it + 1 < TT / 8) {
            const float4* src = pb + (it + 1) * TILE_F4;
            float4* dst = tiles + (s ^ 1) * TILE_F4;
#pragma unroll
            for (int j = 0; j < 8; j++)
                cpa16(smem_u32(&dst[j * 256 + tid]), &src[j * 256 + tid]);
            CPA_COMMIT();
            asm volatile("cp.async.wait_group 1;" ::: "memory");
        } else {
            asm volatile("cp.async.wait_group 0;" ::: "memory");
        }
        __syncthreads();

        const float4* tile = tiles + s * TILE_F4;

        float partial = 0.f;
#pragma unroll
        for (int k = 0; k < 8; k++) {
            float4 a  = tile[w * 256 + k * 32 + lane];
            float4 uu = u_s[k * 32 + lane];
            partial += a.x * uu.x + a.y * uu.y + a.z * uu.z + a.w * uu.w;
        }
#pragma unroll
        for (int off = 16; off; off >>= 1)
            partial += __shfl_xor_sync(0xffffffffu, partial, off);
        if (lane == 0) s_sm[w] = partial;
        __syncthreads();

        float s0[8], wv[8];
        float tmax = -INFINITY;
#pragma unroll
        for (int i = 0; i < 8; i++) { s0[i] = s_sm[i]; tmax = fmaxf(tmax, s0[i]); }
        float m_new = fmaxf(m, tmax);
        float cf = __expf(m - m_new);
        float wsum = 0.f;
#pragma unroll
        for (int i = 0; i < 8; i++) { wv[i] = __expf(s0[i] - m_new); wsum += wv[i]; }
        l = l * cf + wsum;
        m = m_new;
        acc.x *= cf; acc.y *= cf; acc.z *= cf; acc.w *= cf;

#pragma unroll
        for (int i = 0; i < 8; i++) {
            float4 v = tile[i * 256 + tid];
            acc.x += wv[i] * v.x;
            acc.y += wv[i] * v.y;
            acc.z += wv[i] * v.z;
            acc.w += wv[i] * v.w;
        }
        __syncthreads();
    }

    float inv = 1.f / l;
    reinterpret_cast<float4*>(c + (size_t)b * FF)[tid] =
        make_float4(acc.x * inv, acc.y * inv, acc.z * inv, acc.w * inv);
}

// ---------------------------------------------------------------------------
// kernel_launch
// Inputs: 0=z_state[512,1024] 1=past_predictions[512,256,1024]
//         2=Wq[1024,1024] 3=Wk[1024,1024] 4=Wv[1024,1024]
//         5=bq[1024] 6=bk[1024] 7=bv[1024]
// Output: context [512,1024] fp32
// ---------------------------------------------------------------------------
extern "C" void kernel_launch(void* const* d_in, const int* in_sizes, int n_in,
                              void* d_out, int out_size)
{
    const float* z    = (const float*)d_in[0];
    const float* past = (const float*)d_in[1];
    const float* Wq   = (const float*)d_in[2];
    const float* Wk   = (const float*)d_in[3];
    const float* Wv   = (const float*)d_in[4];
    const float* bq   = (const float*)d_in[5];
    // bk (d_in[6]) is softmax-invariant — unused.
    const float* bv   = (const float*)d_in[7];
    float* out = (float*)d_out;

    void *xa, *xb, *w2, *up, *cp;
    cudaGetSymbolAddress(&xa, g_xa);
    cudaGetSymbolAddress(&xb, g_xb);
    cudaGetSymbolAddress(&w2, g_w2);
    cudaGetSymbolAddress(&up, g_u);
    cudaGetSymbolAddress(&cp, g_c);
    __nv_bfloat16* xa_p = (__nv_bfloat16*)xa;
    __nv_bfloat16* xb_p = (__nv_bfloat16*)xb;
    __nv_bfloat16* w2_p = (__nv_bfloat16*)w2;
    float* u_buf = (float*)up;
    float* c_buf = (float*)cp;

    const int attn_smem = (256 + 2 * TILE_F4) * sizeof(float4) + 32 * sizeof(float);
    cudaFuncSetAttribute(attn_kernel,
                         cudaFuncAttributeMaxDynamicSharedMemorySize, attn_smem);
    cudaFuncSetAttribute(mma_gemm<true, true>,
                         cudaFuncAttributeMaxDynamicSharedMemorySize, SMEM_GEMM);
    cudaFuncSetAttribute(mma_gemm<false, false>,
                         cudaFuncAttributeMaxDynamicSharedMemorySize, SMEM_GEMM);
    cudaFuncSetAttribute(mma_gemm<true, false>,
                         cudaFuncAttributeMaxDynamicSharedMemorySize, SMEM_GEMM);

    dim3 gg(FF / 64, BB / 128);   // (16, 4) = 64 CTAs

    // split operands for GEMM1
    split_mat<false><<<BB, 256>>>((const float4*)z, xa_p);
    split_mat<true><<<FF, 256>>>((const float4*)Wq, w2_p);
    // q = z @ Wq^T + bq  -> A-side bf16 split directly into xb
    mma_gemm<true, true><<<gg, 256, SMEM_GEMM>>>(xa_p, w2_p, bq, xb_p);
    // Wk used untransposed (u = q @ Wk): transpose-split (B-side)
    splitT_mat<<<dim3(32, 32), 256>>>(Wk, w2_p);
    // u = q @ Wk (fp32)
    mma_gemm<false, false><<<gg, 256, SMEM_GEMM>>>(xb_p, w2_p, nullptr, u_buf);
    // prep Wv split (w2 free after GEMM2)
    split_mat<true><<<FF, 256>>>((const float4*)Wv, w2_p);
    // c[b] = softmax_t(u[b].p[b,t]) . p[b]
    attn_kernel<<<BB, 256, attn_smem>>>(u_buf, past, c_buf);
    // split(c) (A-side)
    split_mat<false><<<BB, 256>>>((const float4*)c_buf, xa_p);
    // out = c @ Wv^T + bv (fp32)
    mma_gemm<true, false><<<gg, 256, SMEM_GEMM>>>(xa_p, w2_p, bv, out);
}

// round 10
// speedup vs baseline: 1.6353x; 1.3981x over previous
#include <cuda_runtime.h>
#include <cuda_bf16.h>
#include <math.h>
#include <cstdint>

// Shapes (fixed per reference): B=512, T=256, F=D=1024
#define BB 512
#define TT 256
#define FF 1024

// ---------------- scratch (__device__ globals; no allocs allowed) -----------
// Split matrices stored TILED: block (rb, s) = rows [rb*64,rb*64+64) x k [s*64,s*64+64)
//   -> 16 KB: [hi tile 8KB][lo tile 8KB], each tile 64 rows x 128B, XOR-swizzled.
__device__ __align__(16) __nv_bfloat16 g_xa[BB * 2048];  // split(z)/split(c): 2MB
__device__ __align__(16) __nv_bfloat16 g_xb[BB * 2048];  // split(q): 2MB
__device__ __align__(16) __nv_bfloat16 g_w2[FF * 2048];  // split(W*): 4MB (reused)
__device__ float g_u[BB * FF];
__device__ float g_c[BB * FF];

// ---------------- ptx helpers ----------------------------------------------
__device__ __forceinline__ uint32_t smem_u32(const void* p) {
    uint32_t a;
    asm("{ .reg .u64 t; cvta.to.shared.u64 t, %1; cvt.u32.u64 %0, t; }"
        : "=r"(a) : "l"(p));
    return a;
}
__device__ __forceinline__ void ldsm_x4(uint32_t (&r)[4], uint32_t addr) {
    asm volatile("ldmatrix.sync.aligned.m8n8.x4.shared.b16 {%0,%1,%2,%3}, [%4];"
                 : "=r"(r[0]), "=r"(r[1]), "=r"(r[2]), "=r"(r[3]) : "r"(addr));
}
__device__ __forceinline__ void mma_bf16(float (&d)[4], const uint32_t (&a)[4],
                                         uint32_t b0, uint32_t b1) {
    asm volatile(
        "mma.sync.aligned.m16n8k16.row.col.f32.bf16.bf16.f32 "
        "{%0,%1,%2,%3}, {%4,%5,%6,%7}, {%8,%9}, {%0,%1,%2,%3};"
        : "+f"(d[0]), "+f"(d[1]), "+f"(d[2]), "+f"(d[3])
        : "r"(a[0]), "r"(a[1]), "r"(a[2]), "r"(a[3]), "r"(b0), "r"(b1));
}

#define MBAR_INIT(a, c) asm volatile("mbarrier.init.shared.b64 [%0], %1;" :: "r"(a), "r"(c) : "memory")
#define MBAR_EXPECT(a, tx) asm volatile("mbarrier.arrive.expect_tx.shared.b64 _, [%0], %1;" :: "r"(a), "r"(tx) : "memory")
#define FENCE_ASYNC() asm volatile("fence.proxy.async.shared::cta;" ::: "memory")

__device__ __forceinline__ void bulk_g2s(uint32_t dst, const void* src,
                                         uint32_t bytes, uint32_t mbar) {
    asm volatile(
        "cp.async.bulk.shared::cluster.global.mbarrier::complete_tx::bytes "
        "[%0], [%1], %2, [%3];"
        :: "r"(dst), "l"(src), "r"(bytes), "r"(mbar) : "memory");
}

#define MBAR_WAIT(a, ph) do {                                                    \
    uint32_t _m = (a), _p = (ph), _d;                                            \
    asm volatile("{\n\t.reg .pred p;\n\t"                                        \
        "mbarrier.try_wait.parity.acquire.cta.shared::cta.b64 p, [%1], %2;\n\t"  \
        "selp.b32 %0, 1, 0, p;\n\t}" : "=r"(_d) : "r"(_m), "r"(_p) : "memory");  \
    if (!_d) {                                                                   \
        asm volatile("{\n\t.reg .pred P1;\n\t"                                   \
            "W%=:\n\t"                                                           \
            "mbarrier.try_wait.parity.acquire.cta.shared::cta.b64 P1, [%0], %1, 0x989680;\n\t" \
            "@P1 bra.uni D%=;\n\t"                                               \
            "bra.uni W%=;\n\t"                                                   \
            "D%=:\n\t}" :: "r"(_m), "r"(_p) : "memory");                         \
    }                                                                            \
} while (0)

// ---------------- fp32 -> bf16 hi/lo split + tiled addressing ----------------
__device__ __forceinline__ void split1(float x, __nv_bfloat16& h, __nv_bfloat16& l) {
    h = __float2bfloat16(x);
    l = __float2bfloat16(x - __bfloat162float(h));
}
__device__ __forceinline__ uint32_t pack_bf(__nv_bfloat16 a, __nv_bfloat16 b) {
    return (uint32_t)__bfloat16_as_ushort(a) | ((uint32_t)__bfloat16_as_ushort(b) << 16);
}
// byte offset of (row, kcol, part) in a tiled split array
__device__ __forceinline__ size_t tiled_off(int row, int kcol, int part) {
    int tb = (row >> 6) * 16 + (kcol >> 6);
    int r = row & 63, c = kcol & 63;
    return (size_t)tb * 16384 + (size_t)part * 8192
         + (size_t)(r * 128 + ((((c >> 3) ^ (r & 7))) << 4) + (c & 7) * 2);
}

// in: fp32 [R][1024] -> tiled split array. grid = R blocks, 256 thr.
__global__ __launch_bounds__(256)
void split_mat(const float4* __restrict__ in, char* __restrict__ out)
{
    int i = blockIdx.x * 256 + threadIdx.x;
    float4 v = in[i];
    int r = i >> 8, c4 = (i & 255) * 4;
    __nv_bfloat16 h0, h1, h2, h3, l0, l1, l2, l3;
    split1(v.x, h0, l0); split1(v.y, h1, l1);
    split1(v.z, h2, l2); split1(v.w, h3, l3);
    uint2 hv, lv;
    hv.x = pack_bf(h0, h1); hv.y = pack_bf(h2, h3);
    lv.x = pack_bf(l0, l1); lv.y = pack_bf(l2, l3);
    *reinterpret_cast<uint2*>(out + tiled_off(r, c4, 0)) = hv;
    *reinterpret_cast<uint2*>(out + tiled_off(r, c4, 1)) = lv;
}

// Wk is [K=1024][N=1024]; tiled split of Wk^T (row = n, kcol = k). grid (32,32).
__global__ __launch_bounds__(256)
void splitT_mat(const float* __restrict__ W, char* __restrict__ out)
{
    __shared__ float t[32][33];
    int tx = threadIdx.x & 31, ty = threadIdx.x >> 5;   // ty 0..7
    int k0 = blockIdx.x * 32, n0 = blockIdx.y * 32;
#pragma unroll
    for (int i = 0; i < 4; i++)
        t[ty * 4 + i][tx] = W[(size_t)(k0 + ty * 4 + i) * FF + n0 + tx];
    __syncthreads();
    // thread -> row n0+tx, 4 consecutive k = k0+ty*4..+3
    __nv_bfloat16 h[4], l[4];
#pragma unroll
    for (int i = 0; i < 4; i++) split1(t[ty * 4 + i][tx], h[i], l[i]);
    uint2 hv, lv;
    hv.x = pack_bf(h[0], h[1]); hv.y = pack_bf(h[2], h[3]);
    lv.x = pack_bf(l[0], l[1]); lv.y = pack_bf(l[2], l[3]);
    int n = n0 + tx, kk = k0 + ty * 4;
    *reinterpret_cast<uint2*>(out + tiled_off(n, kk, 0)) = hv;
    *reinterpret_cast<uint2*>(out + tiled_off(n, kk, 1)) = lv;
}

// ---------------------------------------------------------------------------
// HMMA bf16 NT GEMM on tiled split operands, bulk-copy pipeline.
//   D[512][1024] = (Ahi+Alo)[512][1024] @ ((Bhi+Blo)[1024][1024])^T  (3 passes,
//   drops lo*lo). CTA tile 64x64, grid (16,8)=128 CTAs, 8 warps (2M x 4N),
//   warp tile 32x16. 16 stages of BK=64; 3-slot smem ring, 32KB/slot
//   ([Ahi|Alo|Bhi|Blo] 8KB each), filled by 2 cp.async.bulk per stage.
// OUTMODE 0: fp32 [512][1024] (+bias).  1: tiled split array (+bias).
// ---------------------------------------------------------------------------
#define STG_B 32768
#define SMEM_GEMM (1024 + 3 * STG_B)   // 99328

__device__ __forceinline__ void issue_stage(uint32_t mbar, uint32_t dst,
                                            const char* Atl, const char* Btl,
                                            int mb, int nb, int s)
{
    MBAR_EXPECT(mbar, 32768u);
    bulk_g2s(dst,          Atl + (size_t)(mb * 16 + s) * 16384, 16384u, mbar);
    bulk_g2s(dst + 16384u, Btl + (size_t)(nb * 16 + s) * 16384, 16384u, mbar);
}

template <bool HASBIAS, int OUTMODE>
__global__ __launch_bounds__(256)
void mma_gemm(const char* __restrict__ Atl, const char* __restrict__ Btl,
              const float* __restrict__ bias, void* __restrict__ Out)
{
    extern __shared__ char smem[];
    const uint32_t sb = smem_u32(smem);
    const int tid  = threadIdx.x;
    const int wid  = tid >> 5;
    const int lane = tid & 31;
    const int wm = wid >> 2;       // 2 M groups of 32 rows
    const int wn = wid & 3;        // 4 N groups of 16 cols
    const int nb = blockIdx.x;
    const int mb = blockIdx.y;

    const uint32_t tiles = sb + 1024;

    if (tid == 0) {
#pragma unroll
        for (int j = 0; j < 3; j++) MBAR_INIT(sb + 8 * j, 1);
        FENCE_ASYNC();
    }
    __syncthreads();
    if (tid == 0) {
#pragma unroll
        for (int p = 0; p < 3; p++)
            issue_stage(sb + 8 * p, tiles + p * STG_B, Atl, Btl, mb, nb, p);
    }

    // ldmatrix per-thread geometry
    const int q  = lane >> 3;
    const int lr = lane & 7;
    const int rowA0 = wm * 32 + (q & 1) * 8 + lr;        // mf adds 16
    const int rowB  = wn * 16 + (q >> 1) * 8 + lr;
    const uint32_t arow0 = rowA0 * 128, arow1 = (rowA0 + 16) * 128;
    const uint32_t brow  = rowB * 128;
    const int a0m = rowA0 & 7, a1m = (rowA0 + 16) & 7, bm = rowB & 7;
    const int qk = q >> 1, qb = q & 1;

    float acc[2][2][4];
#pragma unroll
    for (int i = 0; i < 2; i++)
#pragma unroll
        for (int j = 0; j < 2; j++)
#pragma unroll
            for (int e = 0; e < 4; e++) acc[i][j][e] = 0.f;

    for (int s = 0; s < 16; s++) {
        const int slot = s % 3;
        MBAR_WAIT(sb + 8 * slot, (s / 3) & 1);
        const uint32_t stg = tiles + slot * STG_B;

#pragma unroll
        for (int pass = 0; pass < 3; pass++) {
            const uint32_t ab = stg + ((pass == 1) ? 8192u : 0u);
            const uint32_t bb = stg + 16384u + ((pass == 2) ? 8192u : 0u);
#pragma unroll
            for (int kk = 0; kk < 4; kk++) {
                uint32_t a0[4], a1[4], b0[4];
                ldsm_x4(a0, ab + arow0 + (uint32_t)(((2 * kk + qk) ^ a0m) << 4));
                ldsm_x4(a1, ab + arow1 + (uint32_t)(((2 * kk + qk) ^ a1m) << 4));
                ldsm_x4(b0, bb + brow  + (uint32_t)(((2 * kk + qb) ^ bm)  << 4));
                mma_bf16(acc[0][0], a0, b0[0], b0[1]);
                mma_bf16(acc[0][1], a0, b0[2], b0[3]);
                mma_bf16(acc[1][0], a1, b0[0], b0[1]);
                mma_bf16(acc[1][1], a1, b0[2], b0[3]);
            }
        }
        __syncthreads();   // all warps done reading this slot
        if (tid == 0 && s + 3 < 16)
            issue_stage(sb + 8 * slot, stg, Atl, Btl, mb, nb, s + 3);
    }

    // epilogue: thread -> rows mb*64 + wm*32 + mf*16 + {lane/4, +8},
    //           cols nb*64 + wn*16 + nf*8 + 2*(lane%3mask)
    const int r0 = mb * 64 + wm * 32 + (lane >> 2);
    const int cb = nb * 64 + wn * 16 + 2 * (lane & 3);
#pragma unroll
    for (int mf = 0; mf < 2; mf++) {
        const int rowA = r0 + mf * 16;
        const int rowB2 = rowA + 8;
#pragma unroll
        for (int nf = 0; nf < 2; nf++) {
            const int col = cb + nf * 8;
            float bx = 0.f, by = 0.f;
            if (HASBIAS) { bx = bias[col]; by = bias[col + 1]; }
            float d0 = acc[mf][nf][0] + bx, d1 = acc[mf][nf][1] + by;
            float d2 = acc[mf][nf][2] + bx, d3 = acc[mf][nf][3] + by;
            if (OUTMODE == 1) {
                char* o2 = (char*)Out;
                __nv_bfloat16 h0, h1, h2, h3, l0, l1, l2, l3;
                split1(d0, h0, l0); split1(d1, h1, l1);
                split1(d2, h2, l2); split1(d3, h3, l3);
                *reinterpret_cast<uint32_t*>(o2 + tiled_off(rowA, col, 0))  = pack_bf(h0, h1);
                *reinterpret_cast<uint32_t*>(o2 + tiled_off(rowA, col, 1))  = pack_bf(l0, l1);
                *reinterpret_cast<uint32_t*>(o2 + tiled_off(rowB2, col, 0)) = pack_bf(h2, h3);
                *reinterpret_cast<uint32_t*>(o2 + tiled_off(rowB2, col, 1)) = pack_bf(l2, l3);
            } else {
                float* o = (float*)Out;
                *reinterpret_cast<float2*>(o + (size_t)rowA * FF + col)  = make_float2(d0, d1);
                *reinterpret_cast<float2*>(o + (size_t)rowB2 * FF + col) = make_float2(d2, d3);
            }
        }
    }
}

// ---------------------------------------------------------------------------
// Fused single-query attention: one cp.async.bulk (32KB) per 8-row tile,
// 2-slot mbarrier ring, online softmax, single HBM pass over p.
// smem: [0,16) mbars | [64,96) s_sm | [1024,5120) u | [5120,+64K) tiles
// ---------------------------------------------------------------------------
#define ATTN_SMEM (5120 + 2 * 32768)   // 70656

__global__ __launch_bounds__(256)
void attn_kernel(const float* __restrict__ u, const float* __restrict__ p,
                 float* __restrict__ c)
{
    extern __shared__ char smem[];
    const uint32_t sb = smem_u32(smem);
    float*  s_sm = (float*)(smem + 64);
    float4* u_s  = (float4*)(smem + 1024);

    const int b    = blockIdx.x;
    const int tid  = threadIdx.x;
    const int lane = tid & 31;
    const int w    = tid >> 5;

    if (tid == 0) {
        MBAR_INIT(sb + 0, 1);
        MBAR_INIT(sb + 8, 1);
        FENCE_ASYNC();
    }
    u_s[tid] = reinterpret_cast<const float4*>(u + (size_t)b * FF)[tid];
    __syncthreads();

    const char* pb = (const char*)(p + (size_t)b * TT * FF);
    if (tid == 0) {
        MBAR_EXPECT(sb + 0, 32768u);
        bulk_g2s(sb + 5120, pb, 32768u, sb + 0);
        MBAR_EXPECT(sb + 8, 32768u);
        bulk_g2s(sb + 5120 + 32768, pb + 32768, 32768u, sb + 8);
    }

    float4 acc = make_float4(0.f, 0.f, 0.f, 0.f);
    float m = -INFINITY;
    float l = 0.f;

    for (int it = 0; it < TT / 8; it++) {
        const int slot = it & 1;
        MBAR_WAIT(sb + 8 * slot, (it >> 1) & 1);
        const float4* tile = (const float4*)(smem + 5120 + slot * 32768);

        // scores: warp w computes dot(u, local row w)
        float partial = 0.f;
#pragma unroll
        for (int k = 0; k < 8; k++) {
            float4 a  = tile[w * 256 + k * 32 + lane];
            float4 uu = u_s[k * 32 + lane];
            partial += a.x * uu.x + a.y * uu.y + a.z * uu.z + a.w * uu.w;
        }
#pragma unroll
        for (int off = 16; off; off >>= 1)
            partial += __shfl_xor_sync(0xffffffffu, partial, off);
        if (lane == 0) s_sm[w] = partial;
        __syncthreads();

        // online softmax (redundant per thread, identical values)
        float s0[8], wv[8];
        float tmax = -INFINITY;
#pragma unroll
        for (int i = 0; i < 8; i++) { s0[i] = s_sm[i]; tmax = fmaxf(tmax, s0[i]); }
        float m_new = fmaxf(m, tmax);
        float cf = __expf(m - m_new);   // it=0: exp(-inf)=0, acc is 0 anyway
        float wsum = 0.f;
#pragma unroll
        for (int i = 0; i < 8; i++) { wv[i] = __expf(s0[i] - m_new); wsum += wv[i]; }
        l = l * cf + wsum;
        m = m_new;
        acc.x *= cf; acc.y *= cf; acc.z *= cf; acc.w *= cf;

#pragma unroll
        for (int i = 0; i < 8; i++) {
            float4 v = tile[i * 256 + tid];
            acc.x += wv[i] * v.x;
            acc.y += wv[i] * v.y;
            acc.z += wv[i] * v.z;
            acc.w += wv[i] * v.w;
        }
        __syncthreads();   // everyone done with this slot (and s_sm)

        if (tid == 0 && it + 2 < TT / 8) {
            MBAR_EXPECT(sb + 8 * slot, 32768u);
            bulk_g2s(sb + 5120 + slot * 32768, pb + (size_t)(it + 2) * 32768,
                     32768u, sb + 8 * slot);
        }
    }

    float inv = 1.f / l;
    reinterpret_cast<float4*>(c + (size_t)b * FF)[tid] =
        make_float4(acc.x * inv, acc.y * inv, acc.z * inv, acc.w * inv);
}

// ---------------------------------------------------------------------------
// kernel_launch
// Inputs: 0=z_state[512,1024] 1=past_predictions[512,256,1024]
//         2=Wq[1024,1024] 3=Wk[1024,1024] 4=Wv[1024,1024]
//         5=bq[1024] 6=bk[1024] 7=bv[1024]
// Output: context [512,1024] fp32
// ---------------------------------------------------------------------------
extern "C" void kernel_launch(void* const* d_in, const int* in_sizes, int n_in,
                              void* d_out, int out_size)
{
    const float* z    = (const float*)d_in[0];
    const float* past = (const float*)d_in[1];
    const float* Wq   = (const float*)d_in[2];
    const float* Wk   = (const float*)d_in[3];
    const float* Wv   = (const float*)d_in[4];
    const float* bq   = (const float*)d_in[5];
    // bk (d_in[6]) is softmax-invariant — unused.
    const float* bv   = (const float*)d_in[7];
    float* out = (float*)d_out;

    void *xa, *xb, *w2, *up, *cp;
    cudaGetSymbolAddress(&xa, g_xa);
    cudaGetSymbolAddress(&xb, g_xb);
    cudaGetSymbolAddress(&w2, g_w2);
    cudaGetSymbolAddress(&up, g_u);
    cudaGetSymbolAddress(&cp, g_c);
    char* xa_p = (char*)xa;
    char* xb_p = (char*)xb;
    char* w2_p = (char*)w2;
    float* u_buf = (float*)up;
    float* c_buf = (float*)cp;

    cudaFuncSetAttribute(attn_kernel,
                         cudaFuncAttributeMaxDynamicSharedMemorySize, ATTN_SMEM);
    cudaFuncSetAttribute(mma_gemm<true, 1>,
                         cudaFuncAttributeMaxDynamicSharedMemorySize, SMEM_GEMM);
    cudaFuncSetAttribute(mma_gemm<false, 0>,
                         cudaFuncAttributeMaxDynamicSharedMemorySize, SMEM_GEMM);
    cudaFuncSetAttribute(mma_gemm<true, 0>,
                         cudaFuncAttributeMaxDynamicSharedMemorySize, SMEM_GEMM);

    dim3 gg(FF / 64, BB / 64);   // (16, 8) = 128 CTAs

    // split operands for GEMM1
    split_mat<<<BB, 256>>>((const float4*)z, xa_p);
    split_mat<<<FF, 256>>>((const float4*)Wq, w2_p);
    // q = z @ Wq^T + bq  -> tiled bf16 split directly into xb
    mma_gemm<true, 1><<<gg, 256, SMEM_GEMM>>>(xa_p, w2_p, bq, xb_p);
    // Wk used untransposed (u = q @ Wk): transpose-split
    splitT_mat<<<dim3(32, 32), 256>>>(Wk, w2_p);
    // u = q @ Wk (fp32)
    mma_gemm<false, 0><<<gg, 256, SMEM_GEMM>>>(xb_p, w2_p, nullptr, u_buf);
    // prep Wv split (w2 free after GEMM2)
    split_mat<<<FF, 256>>>((const float4*)Wv, w2_p);
    // c[b] = softmax_t(u[b].p[b,t]) . p[b]
    attn_kernel<<<BB, 256, ATTN_SMEM>>>(u_buf, past, c_buf);
    // split(c)
    split_mat<<<BB, 256>>>((const float4*)c_buf, xa_p);
    // out = c @ Wv^T + bv (fp32)
    mma_gemm<true, 0><<<gg, 256, SMEM_GEMM>>>(xa_p, w2_p, bv, out);
}